// round 4
// baseline (speedup 1.0000x reference)
#include <cuda_runtime.h>

// x: (B=16, C=512, H=62, W=62) fp32, row-major.
// 9 regions: 2x2 patches at (y,x), y,x in {0,30,60}. flat base = y*62 + x.
// Patch elements: base, base+1, base+62, base+63. Pairs: (2k, 2k+1).
#define HW      3844
#define WIDTH   62
#define CHN     512
#define NPAIR   8
#define NREG    9
#define NCHUNK  16
#define CPC     32
#define EPSV    1e-6f

__constant__ int c_posbase[9] = {0, 30, 60, 1860, 1890, 1920, 3720, 3750, 3780};
// NEG index table (region -> 5 negative region indices). Verified entry-by-entry
// against reference; region 8 is {2,4,5,6,7} (NOT 8 — 8 is its own positive).
__constant__ int c_negidx[9][5] = {
    {1,3,4,2,6},
    {0,2,3,4,5},
    {0,1,4,5,8},
    {0,1,4,6,7},
    {0,1,3,5,7},
    {1,2,4,7,8},
    {0,3,4,7,8},
    {3,4,5,6,8},
    {2,4,5,6,7}
};

// Partials: [pair][chunk][region][{S,D1,D2}] — fully overwritten every launch.
__device__ float g_partial[NPAIR][NCHUNK][NREG][3];

struct Patch { float a, b, c, d, ss; };

__device__ __forceinline__ Patch load_patch(const float* __restrict__ plane, int base) {
    // base always even -> 8-byte aligned float2 loads
    float2 v01 = *reinterpret_cast<const float2*>(plane + base);
    float2 v23 = *reinterpret_cast<const float2*>(plane + base + WIDTH);
    Patch p;
    p.a = v01.x; p.b = v01.y; p.c = v23.x; p.d = v23.y;
    p.ss = fmaf(p.a, p.a, fmaf(p.b, p.b, fmaf(p.c, p.c, p.d * p.d)));
    return p;
}

// exp(cos(p,q)/TEMP) with clamp cos = dot / max(na*nb, EPS); TEMP = 0.1
__device__ __forceinline__ float cexp(const Patch& p, const Patch& q) {
    float dot = fmaf(p.a, q.a, fmaf(p.b, q.b, fmaf(p.c, q.c, p.d * q.d)));
    float d2  = p.ss * q.ss;                  // (na*nb)^2
    float inv = rsqrtf(d2);
    float cosv = (d2 >= EPSV * EPSV) ? dot * inv : dot * (1.0f / EPSV);
    return __expf(cosv * 10.0f);
}

__global__ __launch_bounds__(NREG * CPC)
void lcl_stage1(const float* __restrict__ x) {
    const int pair  = blockIdx.y;             // 0..7
    const int chunk = blockIdx.x;             // 0..15
    const int r     = threadIdx.x >> 5;       // region = warp id, 0..8
    const int lane  = threadIdx.x & 31;
    const int c     = chunk * CPC + lane;     // channel 0..511

    const float* p1 = x + ((size_t)(2 * pair) * CHN + (size_t)c) * HW;  // batch 2k
    const float* p2 = p1 + (size_t)CHN * HW;                            // batch 2k+1

    const int pb = c_posbase[r];
    Patch a1 = load_patch(p1, pb);
    Patch a2 = load_patch(p2, pb);

    float S  = cexp(a1, a2);
    float D1 = 0.0f, D2 = 0.0f;

#pragma unroll
    for (int n = 0; n < 5; n++) {
        const int nb = c_posbase[c_negidx[r][n]];
        Patch b1 = load_patch(p1, nb);        // i1n patch
        Patch b2 = load_patch(p2, nb);        // i2n patch
        D1 += cexp(a1, b1) + cexp(a1, b2);
        D2 += cexp(a2, b2) + cexp(a2, b1);
    }

#pragma unroll
    for (int o = 16; o; o >>= 1) {
        S  += __shfl_xor_sync(0xffffffffu, S,  o);
        D1 += __shfl_xor_sync(0xffffffffu, D1, o);
        D2 += __shfl_xor_sync(0xffffffffu, D2, o);
    }
    if (lane == 0) {
        g_partial[pair][chunk][r][0] = S;
        g_partial[pair][chunk][r][1] = D1;
        g_partial[pair][chunk][r][2] = D2;
    }
}

__global__ void lcl_stage2(float* __restrict__ out) {
    __shared__ float sh[NPAIR * NREG];
    const int t = threadIdx.x;                // 0..95
    if (t < NPAIR * NREG) {
        const int p = t / NREG;
        const int r = t % NREG;
        float S = 0.0f, D1 = 0.0f, D2 = 0.0f;
#pragma unroll
        for (int ch = 0; ch < NCHUNK; ch++) {
            S  += g_partial[p][ch][r][0];
            D1 += g_partial[p][ch][r][1];
            D2 += g_partial[p][ch][r][2];
        }
        // -log(S/(S+D1)) - log(S/(S+D2))
        sh[t] = logf((S + D1) / S) + logf((S + D2) / S);
    }
    __syncthreads();
    if (t == 0) {
        float tot = 0.0f;
        for (int i = 0; i < NPAIR * NREG; i++) tot += sh[i];
        out[0] = tot * (1.0f / 144.0f);       // / BATCH(16) / N_REGIONS(9)
    }
}

extern "C" void kernel_launch(void* const* d_in, const int* in_sizes, int n_in,
                              void* d_out, int out_size) {
    const float* x = (const float*)d_in[0];
    float* out = (float*)d_out;
    (void)in_sizes; (void)n_in; (void)out_size;

    dim3 grid(NCHUNK, NPAIR, 1);              // 128 blocks
    dim3 block(NREG * CPC, 1, 1);             // 288 threads = 9 warps (1 per region)
    lcl_stage1<<<grid, block>>>(x);
    lcl_stage2<<<1, 96>>>(out);
}

// round 5
// speedup vs baseline: 1.2362x; 1.2362x over previous
#include <cuda_runtime.h>

// x: (B=16, C=512, H=62, W=62) fp32, row-major.
// 9 regions: 2x2 patches at (y,x), y,x in {0,30,60}. flat base = y*62 + x.
// Patch elements: base, base+1, base+62, base+63. Pairs: (2k, 2k+1).
#define HW      3844
#define WIDTH   62
#define CHN     512
#define NPAIR   8
#define NREG    9
#define NCHUNK  16
#define NBLK    (NCHUNK * NPAIR)   // 128
#define EPSV    1e-6f

__constant__ int c_posbase[9] = {0, 30, 60, 1860, 1890, 1920, 3720, 3750, 3780};
// region -> 5 negative region indices (region 8 = {2,4,5,6,7}; verified vs ref)
__constant__ int c_negidx[9][5] = {
    {1,3,4,2,6},
    {0,2,3,4,5},
    {0,1,4,5,8},
    {0,1,4,6,7},
    {0,1,3,5,7},
    {1,2,4,7,8},
    {0,3,4,7,8},
    {3,4,5,6,8},
    {2,4,5,6,7}
};

// Partials: [pair][chunk][region][{S,D1,D2}] — fully overwritten every launch.
__device__ float        g_partial[NPAIR][NCHUNK][NREG][3];
__device__ unsigned int g_count;   // zero-init; last block resets to 0 each launch

struct Patch { float a, b, c, d, ss; };

__device__ __forceinline__ Patch load_patch(const float* __restrict__ plane, int base) {
    // base always even -> 8-byte aligned float2 loads
    float2 v01 = *reinterpret_cast<const float2*>(plane + base);
    float2 v23 = *reinterpret_cast<const float2*>(plane + base + WIDTH);
    Patch p;
    p.a = v01.x; p.b = v01.y; p.c = v23.x; p.d = v23.y;
    p.ss = fmaf(p.a, p.a, fmaf(p.b, p.b, fmaf(p.c, p.c, p.d * p.d)));
    return p;
}

// exp(cos(p,q)/TEMP) with clamp cos = dot / max(na*nb, EPS); TEMP = 0.1
__device__ __forceinline__ float cexp(const Patch& p, const Patch& q) {
    float dot = fmaf(p.a, q.a, fmaf(p.b, q.b, fmaf(p.c, q.c, p.d * q.d)));
    float d2  = p.ss * q.ss;                  // (na*nb)^2
    float inv = rsqrtf(d2);
    float cosv = (d2 >= EPSV * EPSV) ? dot * inv : dot * (1.0f / EPSV);
    return __expf(cosv * 10.0f);
}

__global__ __launch_bounds__(NREG * 32)
void lcl_fused(const float* __restrict__ x, float* __restrict__ out) {
    const int pair  = blockIdx.y;             // 0..7
    const int chunk = blockIdx.x;             // 0..15
    const int tid   = threadIdx.x;
    const int r     = tid >> 5;               // region = warp id, 0..8
    const int lane  = tid & 31;
    const int c     = chunk * 32 + lane;      // channel 0..511

    // Stage patches in smem: [plane][region][lane]; stride 5 words -> conflict-free
    __shared__ Patch shp[2][NREG][32];
    __shared__ float shv[NPAIR * NREG];
    __shared__ int   s_isLast;

    {
        const float* p1 = x + ((size_t)(2 * pair) * CHN + (size_t)c) * HW;  // batch 2k
        const float* p2 = p1 + (size_t)CHN * HW;                            // batch 2k+1
        const int pb = c_posbase[r];
        shp[0][r][lane] = load_patch(p1, pb);   // each warp loads only its region
        shp[1][r][lane] = load_patch(p2, pb);
    }
    __syncthreads();

    const Patch a1 = shp[0][r][lane];
    const Patch a2 = shp[1][r][lane];

    float S  = cexp(a1, a2);
    float D1 = 0.0f, D2 = 0.0f;

#pragma unroll
    for (int n = 0; n < 5; n++) {
        const int j = c_negidx[r][n];
        const Patch b1 = shp[0][j][lane];     // i1n patch
        const Patch b2 = shp[1][j][lane];     // i2n patch
        D1 += cexp(a1, b1) + cexp(a1, b2);
        D2 += cexp(a2, b2) + cexp(a2, b1);
    }

#pragma unroll
    for (int o = 16; o; o >>= 1) {
        S  += __shfl_xor_sync(0xffffffffu, S,  o);
        D1 += __shfl_xor_sync(0xffffffffu, D1, o);
        D2 += __shfl_xor_sync(0xffffffffu, D2, o);
    }
    if (lane == 0) {
        g_partial[pair][chunk][r][0] = S;
        g_partial[pair][chunk][r][1] = D1;
        g_partial[pair][chunk][r][2] = D2;
        __threadfence();                      // make this warp's partials visible
    }
    __syncthreads();

    if (tid == 0)
        s_isLast = (atomicAdd(&g_count, 1u) == NBLK - 1u);
    __syncthreads();

    if (s_isLast) {
        // Final fold: 72 (pair,region) cells, 16 chunk-partials each.
        if (tid < NPAIR * NREG) {
            const int p  = tid / NREG;
            const int rr = tid % NREG;
            float Sx = 0.0f, d1 = 0.0f, d2 = 0.0f;
#pragma unroll
            for (int ch = 0; ch < NCHUNK; ch++) {
                Sx += __ldcg(&g_partial[p][ch][rr][0]);
                d1 += __ldcg(&g_partial[p][ch][rr][1]);
                d2 += __ldcg(&g_partial[p][ch][rr][2]);
            }
            // -log(S/(S+D1)) - log(S/(S+D2))
            shv[tid] = logf((Sx + d1) / Sx) + logf((Sx + d2) / Sx);
        }
        __syncthreads();
        if (tid == 0) {
            float tot = 0.0f;
#pragma unroll
            for (int i = 0; i < NPAIR * NREG; i++) tot += shv[i];
            out[0] = tot * (1.0f / 144.0f);   // / BATCH(16) / N_REGIONS(9)
            g_count = 0;                      // reset for next graph replay
        }
    }
}

extern "C" void kernel_launch(void* const* d_in, const int* in_sizes, int n_in,
                              void* d_out, int out_size) {
    const float* x = (const float*)d_in[0];
    float* out = (float*)d_out;
    (void)in_sizes; (void)n_in; (void)out_size;

    dim3 grid(NCHUNK, NPAIR, 1);              // 128 blocks, one wave on 148 SMs
    dim3 block(NREG * 32, 1, 1);              // 288 threads = 9 warps (1 per region)
    lcl_fused<<<grid, block>>>(x, out);
}